// round 10
// baseline (speedup 1.0000x reference)
#include <cuda_runtime.h>
#include <cstdint>

// Gridding: trilinear scatter of B x N points onto B x 64^3 grids.
// grid flat index = ((b*64 + ix)*64 + iy)*64 + iz

static constexpr int SX = 64;
static constexpr int CELLS_PER_B = SX * SX * SX;  // 262144

__global__ void zero_out_kernel(float4* __restrict__ out, int n4) {
    int i = blockIdx.x * blockDim.x + threadIdx.x;
    if (i < n4) out[i] = make_float4(0.f, 0.f, 0.f, 0.f);
}

// One reduction op adds {a,b} to two adjacent floats (8B-aligned).
__device__ __forceinline__ void red_add_v2(float* addr, float a, float b) {
    asm volatile("red.global.add.v2.f32 [%0], {%1, %2};"
                 :: "l"(addr), "f"(a), "f"(b)
                 : "memory");
}

// One reduction op adds {a,b,c,d} to four adjacent floats (16B-aligned).
__device__ __forceinline__ void red_add_v4(float* addr, float a, float b, float c, float d) {
    asm volatile("red.global.add.v4.f32 [%0], {%1, %2, %3, %4};"
                 :: "l"(addr), "f"(a), "f"(b), "f"(c), "f"(d)
                 : "memory");
}

__global__ void gridding_kernel(const float* __restrict__ pt,
                                float* __restrict__ out,
                                int npts, unsigned int N) {
    int gid = blockIdx.x * blockDim.x + threadIdx.x;
    if (gid >= npts) return;

    unsigned int b = (unsigned int)gid / N;

    const float* p = pt + 3ull * (unsigned int)gid;
    float x = p[0] * 32.f;
    float y = p[1] * 32.f;
    float z = p[2] * 32.f;

    // nz_mask: points exactly at the origin contribute nothing
    if (fabsf(x) + fabsf(y) + fabsf(z) == 0.f) return;

    float fx = floorf(x), fy = floorf(y), fz = floorf(z);
    float tx = x - fx, ty = y - fy, tz = z - fz;
    int ix = (int)fx + 32;
    int iy = (int)fy + 32;
    int iz = (int)fz + 32;

    float wx0 = 1.f - tx, wx1 = tx;
    float wy0 = 1.f - ty, wy1 = ty;
    float wz0 = 1.f - tz, wz1 = tz;

    // inputs are in [-1,1) so lower bounds always hold; only +1 sides can fail
    bool c00 = ((unsigned)ix < (unsigned)SX) & ((unsigned)iy < (unsigned)SX);
    bool c01 = ((unsigned)ix < (unsigned)SX) & ((unsigned)(iy + 1) < (unsigned)SX);
    bool c10 = ((unsigned)(ix + 1) < (unsigned)SX) & ((unsigned)iy < (unsigned)SX);
    bool c11 = ((unsigned)(ix + 1) < (unsigned)SX) & ((unsigned)(iy + 1) < (unsigned)SX);
    bool bz1 = (unsigned)(iz + 1) < (unsigned)SX;

    float w00 = wx0 * wy0;
    float w01 = wx0 * wy1;
    float w10 = wx1 * wy0;
    float w11 = wx1 * wy1;

    float* base = out + (size_t)b * CELLS_PER_B;
    int off00 = ix * 4096 + iy * 64 + iz;

    int izm4 = iz & 3;

    if ((iz & 1) == 0) {
        // even iz: exact 8B-aligned pair, iz+1 <= 63 guaranteed -> one v2 per corner
        if (c00) red_add_v2(base + off00,        w00 * wz0, w00 * wz1);
        if (c01) red_add_v2(base + off00 + 64,   w01 * wz0, w01 * wz1);
        if (c10) red_add_v2(base + off00 + 4096, w10 * wz0, w10 * wz1);
        if (c11) red_add_v2(base + off00 + 4160, w11 * wz0, w11 * wz1);
    } else if (izm4 == 1) {
        // iz % 4 == 1: pair (iz, iz+1) sits in the 16B window starting at iz-1
        // (iz <= 61 in this class, so window [iz-1, iz+2] is in-bounds).
        // Zero lanes add +0.0f exactly -> one v4 per corner.
        int offw = off00 - 1;
        if (c00) red_add_v4(base + offw,        0.f, w00 * wz0, w00 * wz1, 0.f);
        if (c01) red_add_v4(base + offw + 64,   0.f, w01 * wz0, w01 * wz1, 0.f);
        if (c10) red_add_v4(base + offw + 4096, 0.f, w10 * wz0, w10 * wz1, 0.f);
        if (c11) red_add_v4(base + offw + 4160, 0.f, w11 * wz0, w11 * wz1, 0.f);
    } else {
        // iz % 4 == 3: pair straddles two 16B windows -> scalar fallback.
        // (includes iz == 63, where the +1 z-neighbor is out of bounds)
        if (c00) {
            atomicAdd(base + off00,          w00 * wz0);
            if (bz1) atomicAdd(base + off00 + 1,    w00 * wz1);
        }
        if (c01) {
            atomicAdd(base + off00 + 64,     w01 * wz0);
            if (bz1) atomicAdd(base + off00 + 65,   w01 * wz1);
        }
        if (c10) {
            atomicAdd(base + off00 + 4096,   w10 * wz0);
            if (bz1) atomicAdd(base + off00 + 4097, w10 * wz1);
        }
        if (c11) {
            atomicAdd(base + off00 + 4160,   w11 * wz0);
            if (bz1) atomicAdd(base + off00 + 4161, w11 * wz1);
        }
    }
}

extern "C" void kernel_launch(void* const* d_in, const int* in_sizes, int n_in,
                              void* d_out, int out_size) {
    const float* pt = (const float*)d_in[0];
    float* out = (float*)d_out;

    int npts = in_sizes[0] / 3;            // B * N
    int B = out_size / CELLS_PER_B;        // 64
    unsigned int N = (unsigned int)(npts / B);

    // 1) zero the output (poisoned by harness)
    int n4 = out_size / 4;
    {
        int threads = 256;
        int blocks = (n4 + threads - 1) / threads;
        zero_out_kernel<<<blocks, threads>>>((float4*)out, n4);
    }

    // 2) scatter
    {
        int threads = 256;
        int blocks = (npts + threads - 1) / threads;
        gridding_kernel<<<blocks, threads>>>(pt, out, npts, N);
    }
}

// round 13
// speedup vs baseline: 1.0027x; 1.0027x over previous
#include <cuda_runtime.h>
#include <cstdint>

// Gridding: trilinear scatter of B x N points onto B x 64^3 grids.
// grid flat index = ((b*64 + ix)*64 + iy)*64 + iz

static constexpr int SX = 64;
static constexpr int CELLS_PER_B = SX * SX * SX;  // 262144

__global__ void zero_out_kernel(float4* __restrict__ out, int n4) {
    int i = blockIdx.x * blockDim.x + threadIdx.x;
    if (i < n4) out[i] = make_float4(0.f, 0.f, 0.f, 0.f);
}

// One reduction op adds {a,b} to two adjacent floats (8B-aligned).
__device__ __forceinline__ void red_add_v2(float* addr, float a, float b) {
    asm volatile("red.global.add.v2.f32 [%0], {%1, %2};"
                 :: "l"(addr), "f"(a), "f"(b)
                 : "memory");
}

// One reduction op adds {a,b,c,d} to four adjacent floats (16B-aligned).
__device__ __forceinline__ void red_add_v4(float* addr, float a, float b, float c, float d) {
    asm volatile("red.global.add.v4.f32 [%0], {%1, %2, %3, %4};"
                 :: "l"(addr), "f"(a), "f"(b), "f"(c), "f"(d)
                 : "memory");
}

__global__ void gridding_kernel(const float* __restrict__ pt,
                                float* __restrict__ out,
                                int npts, unsigned int N) {
    int gid = blockIdx.x * blockDim.x + threadIdx.x;
    if (gid >= npts) return;

    unsigned int b = (unsigned int)gid / N;

    const float* p = pt + 3ull * (unsigned int)gid;
    float x = p[0] * 32.f;
    float y = p[1] * 32.f;
    float z = p[2] * 32.f;

    // nz_mask: points exactly at the origin contribute nothing
    if (fabsf(x) + fabsf(y) + fabsf(z) == 0.f) return;

    float fx = floorf(x), fy = floorf(y), fz = floorf(z);
    float tx = x - fx, ty = y - fy, tz = z - fz;
    int ix = (int)fx + 32;
    int iy = (int)fy + 32;
    int iz = (int)fz + 32;

    float wx0 = 1.f - tx, wx1 = tx;
    float wy0 = 1.f - ty, wy1 = ty;
    float wz0 = 1.f - tz, wz1 = tz;

    // inputs are in [-1,1) so lower bounds always hold; only +1 sides can fail
    bool c00 = ((unsigned)ix < (unsigned)SX) & ((unsigned)iy < (unsigned)SX);
    bool c01 = ((unsigned)ix < (unsigned)SX) & ((unsigned)(iy + 1) < (unsigned)SX);
    bool c10 = ((unsigned)(ix + 1) < (unsigned)SX) & ((unsigned)iy < (unsigned)SX);
    bool c11 = ((unsigned)(ix + 1) < (unsigned)SX) & ((unsigned)(iy + 1) < (unsigned)SX);
    bool bz1 = (unsigned)(iz + 1) < (unsigned)SX;

    float w00 = wx0 * wy0;
    float w01 = wx0 * wy1;
    float w10 = wx1 * wy0;
    float w11 = wx1 * wy1;

    float* base = out + (size_t)b * CELLS_PER_B;
    int off00 = ix * 4096 + iy * 64 + iz;

    int izm4 = iz & 3;

    if ((iz & 1) == 0) {
        // even iz: exact 8B-aligned pair, iz+1 <= 63 guaranteed -> one v2 per corner
        if (c00) red_add_v2(base + off00,        w00 * wz0, w00 * wz1);
        if (c01) red_add_v2(base + off00 + 64,   w01 * wz0, w01 * wz1);
        if (c10) red_add_v2(base + off00 + 4096, w10 * wz0, w10 * wz1);
        if (c11) red_add_v2(base + off00 + 4160, w11 * wz0, w11 * wz1);
    } else if (izm4 == 1) {
        // iz % 4 == 1: pair (iz, iz+1) sits in the 16B window starting at iz-1
        // (iz <= 61 in this class, so window [iz-1, iz+2] is in-bounds).
        // Zero lanes add +0.0f exactly -> one v4 per corner.
        int offw = off00 - 1;
        if (c00) red_add_v4(base + offw,        0.f, w00 * wz0, w00 * wz1, 0.f);
        if (c01) red_add_v4(base + offw + 64,   0.f, w01 * wz0, w01 * wz1, 0.f);
        if (c10) red_add_v4(base + offw + 4096, 0.f, w10 * wz0, w10 * wz1, 0.f);
        if (c11) red_add_v4(base + offw + 4160, 0.f, w11 * wz0, w11 * wz1, 0.f);
    } else {
        // iz % 4 == 3: pair straddles two 16B windows -> scalar fallback.
        // (includes iz == 63, where the +1 z-neighbor is out of bounds)
        if (c00) {
            atomicAdd(base + off00,          w00 * wz0);
            if (bz1) atomicAdd(base + off00 + 1,    w00 * wz1);
        }
        if (c01) {
            atomicAdd(base + off00 + 64,     w01 * wz0);
            if (bz1) atomicAdd(base + off00 + 65,   w01 * wz1);
        }
        if (c10) {
            atomicAdd(base + off00 + 4096,   w10 * wz0);
            if (bz1) atomicAdd(base + off00 + 4097, w10 * wz1);
        }
        if (c11) {
            atomicAdd(base + off00 + 4160,   w11 * wz0);
            if (bz1) atomicAdd(base + off00 + 4161, w11 * wz1);
        }
    }
}

extern "C" void kernel_launch(void* const* d_in, const int* in_sizes, int n_in,
                              void* d_out, int out_size) {
    const float* pt = (const float*)d_in[0];
    float* out = (float*)d_out;

    int npts = in_sizes[0] / 3;            // B * N
    int B = out_size / CELLS_PER_B;        // 64
    unsigned int N = (unsigned int)(npts / B);

    // 1) zero the output (poisoned by harness)
    int n4 = out_size / 4;
    {
        int threads = 256;
        int blocks = (n4 + threads - 1) / threads;
        zero_out_kernel<<<blocks, threads>>>((float4*)out, n4);
    }

    // 2) scatter
    {
        int threads = 256;
        int blocks = (npts + threads - 1) / threads;
        gridding_kernel<<<blocks, threads>>>(pt, out, npts, N);
    }
}

// round 14
// speedup vs baseline: 1.0033x; 1.0006x over previous
#include <cuda_runtime.h>
#include <cstdint>

// Gridding: trilinear scatter of B x N points onto B x 64^3 grids.
// grid flat index = ((b*64 + ix)*64 + iy)*64 + iz

static constexpr int SX = 64;
static constexpr int CELLS_PER_B = SX * SX * SX;  // 262144

__global__ void zero_out_kernel(float4* __restrict__ out, int n4) {
    int i = blockIdx.x * blockDim.x + threadIdx.x;
    if (i < n4) out[i] = make_float4(0.f, 0.f, 0.f, 0.f);
}

// One reduction op adds {a,b} to two adjacent floats (8B-aligned).
__device__ __forceinline__ void red_add_v2(float* addr, float a, float b) {
    asm volatile("red.global.add.v2.f32 [%0], {%1, %2};"
                 :: "l"(addr), "f"(a), "f"(b)
                 : "memory");
}

// One reduction op adds {a,b,c,d} to four adjacent floats (16B-aligned).
__device__ __forceinline__ void red_add_v4(float* addr, float a, float b, float c, float d) {
    asm volatile("red.global.add.v4.f32 [%0], {%1, %2, %3, %4};"
                 :: "l"(addr), "f"(a), "f"(b), "f"(c), "f"(d)
                 : "memory");
}

__global__ void gridding_kernel(const float* __restrict__ pt,
                                float* __restrict__ out,
                                int npts, unsigned int N) {
    int gid = blockIdx.x * blockDim.x + threadIdx.x;
    if (gid >= npts) return;

    unsigned int b = (unsigned int)gid / N;

    const float* p = pt + 3ull * (unsigned int)gid;
    float x = p[0] * 32.f;
    float y = p[1] * 32.f;
    float z = p[2] * 32.f;

    // nz_mask: points exactly at the origin contribute nothing
    if (fabsf(x) + fabsf(y) + fabsf(z) == 0.f) return;

    float fx = floorf(x), fy = floorf(y), fz = floorf(z);
    float tx = x - fx, ty = y - fy, tz = z - fz;
    int ix = (int)fx + 32;
    int iy = (int)fy + 32;
    int iz = (int)fz + 32;

    float wx0 = 1.f - tx, wx1 = tx;
    float wy0 = 1.f - ty, wy1 = ty;
    float wz0 = 1.f - tz, wz1 = tz;

    // inputs are in [-1,1) so lower bounds always hold; only +1 sides can fail
    bool c00 = ((unsigned)ix < (unsigned)SX) & ((unsigned)iy < (unsigned)SX);
    bool c01 = ((unsigned)ix < (unsigned)SX) & ((unsigned)(iy + 1) < (unsigned)SX);
    bool c10 = ((unsigned)(ix + 1) < (unsigned)SX) & ((unsigned)iy < (unsigned)SX);
    bool c11 = ((unsigned)(ix + 1) < (unsigned)SX) & ((unsigned)(iy + 1) < (unsigned)SX);
    bool bz1 = (unsigned)(iz + 1) < (unsigned)SX;

    float w00 = wx0 * wy0;
    float w01 = wx0 * wy1;
    float w10 = wx1 * wy0;
    float w11 = wx1 * wy1;

    float* base = out + (size_t)b * CELLS_PER_B;
    int off00 = ix * 4096 + iy * 64 + iz;

    int izm4 = iz & 3;

    if ((iz & 1) == 0) {
        // even iz: exact 8B-aligned pair, iz+1 <= 63 guaranteed -> one v2 per corner
        if (c00) red_add_v2(base + off00,        w00 * wz0, w00 * wz1);
        if (c01) red_add_v2(base + off00 + 64,   w01 * wz0, w01 * wz1);
        if (c10) red_add_v2(base + off00 + 4096, w10 * wz0, w10 * wz1);
        if (c11) red_add_v2(base + off00 + 4160, w11 * wz0, w11 * wz1);
    } else if (izm4 == 1) {
        // iz % 4 == 1: pair (iz, iz+1) sits in the 16B window starting at iz-1
        // (iz <= 61 in this class, so window [iz-1, iz+2] is in-bounds).
        // Zero lanes add +0.0f exactly -> one v4 per corner.
        int offw = off00 - 1;
        if (c00) red_add_v4(base + offw,        0.f, w00 * wz0, w00 * wz1, 0.f);
        if (c01) red_add_v4(base + offw + 64,   0.f, w01 * wz0, w01 * wz1, 0.f);
        if (c10) red_add_v4(base + offw + 4096, 0.f, w10 * wz0, w10 * wz1, 0.f);
        if (c11) red_add_v4(base + offw + 4160, 0.f, w11 * wz0, w11 * wz1, 0.f);
    } else {
        // iz % 4 == 3: pair straddles two 16B windows -> scalar fallback.
        // (includes iz == 63, where the +1 z-neighbor is out of bounds)
        if (c00) {
            atomicAdd(base + off00,          w00 * wz0);
            if (bz1) atomicAdd(base + off00 + 1,    w00 * wz1);
        }
        if (c01) {
            atomicAdd(base + off00 + 64,     w01 * wz0);
            if (bz1) atomicAdd(base + off00 + 65,   w01 * wz1);
        }
        if (c10) {
            atomicAdd(base + off00 + 4096,   w10 * wz0);
            if (bz1) atomicAdd(base + off00 + 4097, w10 * wz1);
        }
        if (c11) {
            atomicAdd(base + off00 + 4160,   w11 * wz0);
            if (bz1) atomicAdd(base + off00 + 4161, w11 * wz1);
        }
    }
}

extern "C" void kernel_launch(void* const* d_in, const int* in_sizes, int n_in,
                              void* d_out, int out_size) {
    const float* pt = (const float*)d_in[0];
    float* out = (float*)d_out;

    int npts = in_sizes[0] / 3;            // B * N
    int B = out_size / CELLS_PER_B;        // 64
    unsigned int N = (unsigned int)(npts / B);

    // 1) zero the output (poisoned by harness)
    int n4 = out_size / 4;
    {
        int threads = 256;
        int blocks = (n4 + threads - 1) / threads;
        zero_out_kernel<<<blocks, threads>>>((float4*)out, n4);
    }

    // 2) scatter
    {
        int threads = 256;
        int blocks = (npts + threads - 1) / threads;
        gridding_kernel<<<blocks, threads>>>(pt, out, npts, N);
    }
}